// round 10
// baseline (speedup 1.0000x reference)
#include <cuda_runtime.h>

#define L2E  1.4426950408889634f
#define LN2  0.6931471805599453f
#define BIGQ (-(1 << 27))

typedef unsigned long long u64;

__device__ __forceinline__ float ex2f_(float x){ float r; asm("ex2.approx.f32 %0, %1;" : "=f"(r) : "f"(x)); return r; }
__device__ __forceinline__ float lg2f_(float x){ float r; asm("lg2.approx.f32 %0, %1;" : "=f"(r) : "f"(x)); return r; }
__device__ __forceinline__ u64 pk2(float lo, float hi){ u64 r; asm("mov.b64 %0,{%1,%2};" : "=l"(r) : "f"(lo), "f"(hi)); return r; }
__device__ __forceinline__ void upk2(float& lo, float& hi, u64 v){ asm("mov.b64 {%0,%1},%2;" : "=f"(lo), "=f"(hi) : "l"(v)); }
__device__ __forceinline__ u64 fma2(u64 a, u64 b, u64 c){ u64 r; asm("fma.rn.f32x2 %0,%1,%2,%3;" : "=l"(r) : "l"(a), "l"(b), "l"(c)); return r; }

// exact e * 2^max(dq, -126), e in [1,2), dq <= 0  (pure ALU, no MUFU)
__device__ __forceinline__ float scl_(float e, int dq){
    int d = dq < -126 ? -126 : dq;
    return __uint_as_float(__float_as_uint(e) + ((unsigned)d << 23));
}

// One warp = TWO (a,b) pairs chained in anti-phase (+128 steps), 4 rows/thread.
// 128 blocks x 256 threads: 1 block/SM, exactly 2 warps per SMSP everywhere ->
// co-warp covers single-warp stall bubbles (measured IPC 0.61 @1 warp vs 0.85 @2).
// Weight-domain DP: w = e * 2^q (e float in [1,2), q int32); softmin is an
// exponent-aligned add (pure ALU); one ex2 per cell on the neighbor-independent
// distance term.
__global__ __launch_bounds__(256)
void sdtw_kernel(const float* __restrict__ X, const float* __restrict__ Y,
                 float* __restrict__ out)
{
    // 2 tiles; row j of tile t: sy[t*1152 + (j&3)*256 + c*128 + (j>>2)*4 + k]
    // nsqy = -L2E*|Y[j]|^2 at sy[t*1152 + 1024 + (j&3)*32 + (j>>2)]
    __shared__ __align__(16) float sy[2 * 1152];

    const int tid  = threadIdx.x;
    const int lane = tid & 31;
    const int wid  = tid >> 5;                 // 0..7

    const int b0 = (blockIdx.x & 7) * 2;       // one b-pair per block
    const int a  = (blockIdx.x >> 3) * 8 + wid;

    // load 2 Y tiles (256 rows) with 256 threads: one row each
    {
        int tile = tid >> 7;
        int j    = tid & 127;
        const float* yrow = Y + (size_t)(b0 + tile) * 1024 + j * 8;
        float sq = 0.f;
        int base = tile * 1152 + (j & 3) * 256 + (j >> 2) * 4;
        #pragma unroll
        for (int k = 0; k < 8; ++k) {
            float vv = yrow[k];
            sq = fmaf(vv, vv, sq);
            sy[base + (k >> 2) * 128 + (k & 3)] = vv;
        }
        sy[tile * 1152 + 1024 + (j & 3) * 32 + (j >> 2)] = sq * (-L2E);
    }

    // X: packed xs2 = +2*L2E*x ; nsqx = -L2E*|x|^2  ->  dot result = -L2E*|x-y|^2
    u64   xs2[4][4];
    float nsqx[4];
    {
        const float* xp = X + (size_t)a * 1024 + lane * 32;
        #pragma unroll
        for (int s = 0; s < 4; ++s) {
            float acc = 0.f;
            #pragma unroll
            for (int kp = 0; kp < 4; ++kp) {
                float f0 = xp[s * 8 + 2 * kp];
                float f1 = xp[s * 8 + 2 * kp + 1];
                acc = fmaf(f0, f0, fmaf(f1, f1, acc));
                xs2[s][kp] = pk2(f0 * (2.0f * L2E), f1 * (2.0f * L2E));
            }
            nsqx[s] = acc * (-L2E);
        }
    }
    __syncthreads();

    // DP state: mantissa e in [1,2), exponent q (int). Masked == q very negative.
    float e[2][4];
    int   q[2][4];
    #pragma unroll
    for (int s = 0; s < 4; ++s) {
        e[0][s] = 1.0f; e[1][s] = 1.0f;
        q[0][s] = BIGQ; q[1][s] = BIGQ;
    }

    // Y register pipeline: buffer (p)&3 holds row ja0(p) = p - 4*lane;
    // refilled at the END of each step, after slot 3 (its last reader) is done.
    u64   yp2[4][4];
    float nyq[4];
    #pragma unroll
    for (int b = 0; b < 4; ++b) {
        nyq[b] = 0.f;
        #pragma unroll
        for (int kp = 0; kp < 4; ++kp) yp2[b][kp] = 0ull;
    }

    const int lane4 = lane * 4;

    // prologue: buffer 0 <- row ja0(p=0) = -lane4 (wrapped; real only for lane 0)
    {
        unsigned jb = (unsigned)(-lane4) & 255u;
        int t   = (int)(jb >> 7) * 1152;
        int off = (int)((jb >> 2) & 31u);
        int A   = t + (int)(jb & 3u) * 256 + off * 4;
        float4 c0 = *reinterpret_cast<const float4*>(&sy[A]);
        float4 c1 = *reinterpret_cast<const float4*>(&sy[A + 128]);
        yp2[0][0] = pk2(c0.x, c0.y); yp2[0][1] = pk2(c0.z, c0.w);
        yp2[0][2] = pk2(c1.x, c1.y); yp2[0][3] = pk2(c1.z, c1.w);
        nyq[0] = sy[t + 1024 + (int)(jb & 3u) * 32 + off];
    }

    float shPe = 1.0f;
    int   shPq = BIGQ;
    const int outA = a * 16 + b0;

    for (int p0 = 0; p0 < 384; p0 += 4) {
        const int j0      = p0 - lane4;
        const unsigned jc = (unsigned)j0 & 255u;
        const unsigned jn = (unsigned)(j0 + 4) & 255u;
        const int tOff0   = (int)(jc >> 7) * 1152;
        const int m0      = (int)((jc >> 2) & 31u);
        const int baseY0  = tOff0 + m0 * 4;
        const int qb0     = tOff0 + 1024 + m0;
        const int tOff1   = (int)(jn >> 7) * 1152;
        const int m1      = (int)((jn >> 2) & 31u);
        const int baseY1  = tOff1 + m1 * 4;
        const int qb1     = tOff1 + 1024 + m1;
        const bool bj0    = ((jc & 127u) == 0u);   // per-pair j==0 boundary: fires only at s==u

        #pragma unroll
        for (int u = 0; u < 4; ++u) {
            const int wIdx = u & 1;
            const int rIdx = wIdx ^ 1;

            const float sh1e = __shfl_up_sync(0xffffffffu, e[rIdx][3], 1);
            const int   sh1q = __shfl_up_sync(0xffffffffu, q[rIdx][3], 1);

            // reverse slot order: slot s reads (e,q)[wIdx][s-1] (prev2) before slot s-1 writes
            #pragma unroll
            for (int s = 3; s >= 0; --s) {
                float eu, el, ed;
                int   qu, ql, qd;
                if (s == 0) {
                    eu = sh1e;  qu = (lane == 0) ? BIGQ : sh1q;
                    if (u == 0) {
                        el = e[rIdx][0];  ql = bj0 ? BIGQ : q[rIdx][0];
                        if (lane == 0) { ed = 1.0f;  qd = bj0 ? 0 : BIGQ; }   // corner seed of each pair
                        else           { ed = shPe;  qd = bj0 ? BIGQ : shPq; }
                    } else {
                        el = e[rIdx][0];  ql = q[rIdx][0];
                        ed = shPe;        qd = (lane == 0) ? BIGQ : shPq;
                    }
                } else {
                    eu = e[rIdx][s - 1];  qu = q[rIdx][s - 1];
                    if (s == u) {
                        el = e[rIdx][s];      ql = bj0 ? BIGQ : q[rIdx][s];
                        ed = e[wIdx][s - 1];  qd = bj0 ? BIGQ : q[wIdx][s - 1];
                    } else {
                        el = e[rIdx][s];      ql = q[rIdx][s];
                        ed = e[wIdx][s - 1];  qd = q[wIdx][s - 1];
                    }
                }

                // weight-domain softmin: align exponents to max q, add mantissas.
                int qm = max(max(qu, ql), qd);
                float sum = (scl_(eu, qu - qm) + scl_(el, ql - qm)) + scl_(ed, qd - qm);

                // distance exponent -L2E*|x-y|^2 (neighbor-independent MUFU)
                u64 acc2 = pk2(nsqx[s], nyq[(u - s) & 3]);
                #pragma unroll
                for (int kp = 0; kp < 4; ++kp)
                    acc2 = fma2(xs2[s][kp], yp2[(u - s) & 3][kp], acc2);
                float lo, hi; upk2(lo, hi, acc2);
                float w = sum * ex2f_(lo + hi);     // w in [2^-123, 6): always normal

                // exact exponent/mantissa split
                unsigned wb = __float_as_uint(w);
                q[wIdx][s] = qm + (int)(wb >> 23) - 127;
                e[wIdx][s] = __uint_as_float((wb & 0x007FFFFFu) | 0x3F800000u);
            }

            // refill buffer (u+1)&3 with row j0+u+1 AFTER its last reader (slot 3) is done
            {
                const int A = (u < 3) ? (baseY0 + (u + 1) * 256) : baseY1;
                const int b = (u + 1) & 3;
                float4 c0 = *reinterpret_cast<const float4*>(&sy[A]);
                float4 c1 = *reinterpret_cast<const float4*>(&sy[A + 128]);
                yp2[b][0] = pk2(c0.x, c0.y); yp2[b][1] = pk2(c0.z, c0.w);
                yp2[b][2] = pk2(c1.x, c1.y); yp2[b][3] = pk2(c1.z, c1.w);
                nyq[b] = (u < 3) ? sy[qb0 + (u + 1) * 32] : sy[qb1];
            }

            // harvest: pair A at p=254 (p0=252,u=2), pair B at p=382 (p0=380,u=2)
            if (u == 2 && lane == 31) {
                if (p0 == 252) out[outA]     = -((float)q[0][3] + lg2f_(e[0][3])) * LN2;
                if (p0 == 380) out[outA + 1] = -((float)q[0][3] + lg2f_(e[0][3])) * LN2;
            }

            shPe = sh1e;
            shPq = sh1q;
        }
    }
}

extern "C" void kernel_launch(void* const* d_in, const int* in_sizes, int n_in,
                              void* d_out, int out_size)
{
    const float* X = (const float*)d_in[0];
    const float* Y = (const float*)d_in[1];
    if (n_in >= 2 && in_sizes[0] < in_sizes[1]) {
        const float* t = X; X = Y; Y = t;
    }
    float* out = (float*)d_out;

    // 128 blocks x 256 threads: block = 8 a-values x one b-pair; warp = 2 chained pairs.
    // 1 block/SM -> exactly 2 warps per SMSP on all loaded SMs.
    sdtw_kernel<<<128, 256>>>(X, Y, out);
}

// round 11
// speedup vs baseline: 1.0132x; 1.0132x over previous
#include <cuda_runtime.h>

#define L2E  1.4426950408889634f
#define LN2  0.6931471805599453f
#define BIGQ (-(1 << 27))

typedef unsigned long long u64;

__device__ __forceinline__ float ex2f_(float x){ float r; asm("ex2.approx.f32 %0, %1;" : "=f"(r) : "f"(x)); return r; }
__device__ __forceinline__ float lg2f_(float x){ float r; asm("lg2.approx.f32 %0, %1;" : "=f"(r) : "f"(x)); return r; }
__device__ __forceinline__ u64 pk2(float lo, float hi){ u64 r; asm("mov.b64 %0,{%1,%2};" : "=l"(r) : "f"(lo), "f"(hi)); return r; }
__device__ __forceinline__ void upk2(float& lo, float& hi, u64 v){ asm("mov.b64 {%0,%1},%2;" : "=f"(lo), "=f"(hi) : "l"(v)); }
__device__ __forceinline__ u64 fma2(u64 a, u64 b, u64 c){ u64 r; asm("fma.rn.f32x2 %0,%1,%2,%3;" : "=l"(r) : "l"(a), "l"(b), "l"(c)); return r; }

// exact e * 2^max(dq, -126), e in [1,2), dq <= 0  (pure ALU, no MUFU)
__device__ __forceinline__ float scl_(float e, int dq){
    int d = dq < -126 ? -126 : dq;
    return __uint_as_float(__float_as_uint(e) + ((unsigned)d << 23));
}

// One warp = TWO (a,b) pairs chained in anti-phase (+128 steps), 4 rows/thread.
// 128 blocks x 256 threads: 1 block/SM, exactly 2 warps per SMSP everywhere ->
// co-warp covers single-warp stall bubbles (measured IPC 0.61 @1 warp vs 0.85 @2).
// Weight-domain DP: w = e * 2^q (e float in [1,2), q int32); softmin is an
// exponent-aligned add (pure ALU); one ex2 per cell on the neighbor-independent
// distance term.
__global__ __launch_bounds__(256)
void sdtw_kernel(const float* __restrict__ X, const float* __restrict__ Y,
                 float* __restrict__ out)
{
    // 2 tiles; row j of tile t: sy[t*1152 + (j&3)*256 + c*128 + (j>>2)*4 + k]
    // nsqy = -L2E*|Y[j]|^2 at sy[t*1152 + 1024 + (j&3)*32 + (j>>2)]
    __shared__ __align__(16) float sy[2 * 1152];

    const int tid  = threadIdx.x;
    const int lane = tid & 31;
    const int wid  = tid >> 5;                 // 0..7

    const int b0 = (blockIdx.x & 7) * 2;       // one b-pair per block
    const int a  = (blockIdx.x >> 3) * 8 + wid;

    // load 2 Y tiles (256 rows) with 256 threads: one row each
    {
        int tile = tid >> 7;
        int j    = tid & 127;
        const float* yrow = Y + (size_t)(b0 + tile) * 1024 + j * 8;
        float sq = 0.f;
        int base = tile * 1152 + (j & 3) * 256 + (j >> 2) * 4;
        #pragma unroll
        for (int k = 0; k < 8; ++k) {
            float vv = yrow[k];
            sq = fmaf(vv, vv, sq);
            sy[base + (k >> 2) * 128 + (k & 3)] = vv;
        }
        sy[tile * 1152 + 1024 + (j & 3) * 32 + (j >> 2)] = sq * (-L2E);
    }

    // X: packed xs2 = +2*L2E*x ; nsqx = -L2E*|x|^2  ->  dot result = -L2E*|x-y|^2
    u64   xs2[4][4];
    float nsqx[4];
    {
        const float* xp = X + (size_t)a * 1024 + lane * 32;
        #pragma unroll
        for (int s = 0; s < 4; ++s) {
            float acc = 0.f;
            #pragma unroll
            for (int kp = 0; kp < 4; ++kp) {
                float f0 = xp[s * 8 + 2 * kp];
                float f1 = xp[s * 8 + 2 * kp + 1];
                acc = fmaf(f0, f0, fmaf(f1, f1, acc));
                xs2[s][kp] = pk2(f0 * (2.0f * L2E), f1 * (2.0f * L2E));
            }
            nsqx[s] = acc * (-L2E);
        }
    }
    __syncthreads();

    // DP state: mantissa e in [1,2), exponent q (int). Masked == q very negative.
    float e[2][4];
    int   q[2][4];
    #pragma unroll
    for (int s = 0; s < 4; ++s) {
        e[0][s] = 1.0f; e[1][s] = 1.0f;
        q[0][s] = BIGQ; q[1][s] = BIGQ;
    }

    // Y register pipeline: buffer (p)&3 holds row ja0(p) = p - 4*lane;
    // refilled at the END of each step, after slot 3 (its last reader) is done.
    u64   yp2[4][4];
    float nyq[4];
    #pragma unroll
    for (int b = 0; b < 4; ++b) {
        nyq[b] = 0.f;
        #pragma unroll
        for (int kp = 0; kp < 4; ++kp) yp2[b][kp] = 0ull;
    }

    const int lane4 = lane * 4;

    // prologue: buffer 0 <- row ja0(p=0) = -lane4 (wrapped; real only for lane 0)
    {
        unsigned jb = (unsigned)(-lane4) & 255u;
        int t   = (int)(jb >> 7) * 1152;
        int off = (int)((jb >> 2) & 31u);
        int A   = t + (int)(jb & 3u) * 256 + off * 4;
        float4 c0 = *reinterpret_cast<const float4*>(&sy[A]);
        float4 c1 = *reinterpret_cast<const float4*>(&sy[A + 128]);
        yp2[0][0] = pk2(c0.x, c0.y); yp2[0][1] = pk2(c0.z, c0.w);
        yp2[0][2] = pk2(c1.x, c1.y); yp2[0][3] = pk2(c1.z, c1.w);
        nyq[0] = sy[t + 1024 + (int)(jb & 3u) * 32 + off];
    }

    float shPe = 1.0f;
    int   shPq = BIGQ;
    const int outA = a * 16 + b0;

    for (int p0 = 0; p0 < 384; p0 += 4) {
        const int j0      = p0 - lane4;
        const unsigned jc = (unsigned)j0 & 255u;
        const unsigned jn = (unsigned)(j0 + 4) & 255u;
        const int tOff0   = (int)(jc >> 7) * 1152;
        const int m0      = (int)((jc >> 2) & 31u);
        const int baseY0  = tOff0 + m0 * 4;
        const int qb0     = tOff0 + 1024 + m0;
        const int tOff1   = (int)(jn >> 7) * 1152;
        const int m1      = (int)((jn >> 2) & 31u);
        const int baseY1  = tOff1 + m1 * 4;
        const int qb1     = tOff1 + 1024 + m1;
        const bool bj0    = ((jc & 127u) == 0u);   // per-pair j==0 boundary: fires only at s==u

        #pragma unroll
        for (int u = 0; u < 4; ++u) {
            const int wIdx = u & 1;
            const int rIdx = wIdx ^ 1;

            const float sh1e = __shfl_up_sync(0xffffffffu, e[rIdx][3], 1);
            const int   sh1q = __shfl_up_sync(0xffffffffu, q[rIdx][3], 1);

            // reverse slot order: slot s reads (e,q)[wIdx][s-1] (prev2) before slot s-1 writes
            #pragma unroll
            for (int s = 3; s >= 0; --s) {
                float eu, el, ed;
                int   qu, ql, qd;
                if (s == 0) {
                    eu = sh1e;  qu = (lane == 0) ? BIGQ : sh1q;
                    if (u == 0) {
                        el = e[rIdx][0];  ql = bj0 ? BIGQ : q[rIdx][0];
                        if (lane == 0) { ed = 1.0f;  qd = bj0 ? 0 : BIGQ; }   // corner seed of each pair
                        else           { ed = shPe;  qd = bj0 ? BIGQ : shPq; }
                    } else {
                        el = e[rIdx][0];  ql = q[rIdx][0];
                        ed = shPe;        qd = (lane == 0) ? BIGQ : shPq;
                    }
                } else {
                    eu = e[rIdx][s - 1];  qu = q[rIdx][s - 1];
                    if (s == u) {
                        el = e[rIdx][s];      ql = bj0 ? BIGQ : q[rIdx][s];
                        ed = e[wIdx][s - 1];  qd = bj0 ? BIGQ : q[wIdx][s - 1];
                    } else {
                        el = e[rIdx][s];      ql = q[rIdx][s];
                        ed = e[wIdx][s - 1];  qd = q[wIdx][s - 1];
                    }
                }

                // weight-domain softmin: align exponents to max q, add mantissas.
                int qm = max(max(qu, ql), qd);
                float sum = (scl_(eu, qu - qm) + scl_(el, ql - qm)) + scl_(ed, qd - qm);

                // distance exponent -L2E*|x-y|^2 (neighbor-independent MUFU)
                u64 acc2 = pk2(nsqx[s], nyq[(u - s) & 3]);
                #pragma unroll
                for (int kp = 0; kp < 4; ++kp)
                    acc2 = fma2(xs2[s][kp], yp2[(u - s) & 3][kp], acc2);
                float lo, hi; upk2(lo, hi, acc2);
                float w = sum * ex2f_(lo + hi);     // w in [2^-123, 6): always normal

                // exact exponent/mantissa split
                unsigned wb = __float_as_uint(w);
                q[wIdx][s] = qm + (int)(wb >> 23) - 127;
                e[wIdx][s] = __uint_as_float((wb & 0x007FFFFFu) | 0x3F800000u);
            }

            // refill buffer (u+1)&3 with row j0+u+1 AFTER its last reader (slot 3) is done
            {
                const int A = (u < 3) ? (baseY0 + (u + 1) * 256) : baseY1;
                const int b = (u + 1) & 3;
                float4 c0 = *reinterpret_cast<const float4*>(&sy[A]);
                float4 c1 = *reinterpret_cast<const float4*>(&sy[A + 128]);
                yp2[b][0] = pk2(c0.x, c0.y); yp2[b][1] = pk2(c0.z, c0.w);
                yp2[b][2] = pk2(c1.x, c1.y); yp2[b][3] = pk2(c1.z, c1.w);
                nyq[b] = (u < 3) ? sy[qb0 + (u + 1) * 32] : sy[qb1];
            }

            // harvest: pair A at p=254 (p0=252,u=2), pair B at p=382 (p0=380,u=2)
            if (u == 2 && lane == 31) {
                if (p0 == 252) out[outA]     = -((float)q[0][3] + lg2f_(e[0][3])) * LN2;
                if (p0 == 380) out[outA + 1] = -((float)q[0][3] + lg2f_(e[0][3])) * LN2;
            }

            shPe = sh1e;
            shPq = sh1q;
        }
    }
}

extern "C" void kernel_launch(void* const* d_in, const int* in_sizes, int n_in,
                              void* d_out, int out_size)
{
    const float* X = (const float*)d_in[0];
    const float* Y = (const float*)d_in[1];
    if (n_in >= 2 && in_sizes[0] < in_sizes[1]) {
        const float* t = X; X = Y; Y = t;
    }
    float* out = (float*)d_out;

    // 128 blocks x 256 threads: block = 8 a-values x one b-pair; warp = 2 chained pairs.
    // 1 block/SM -> exactly 2 warps per SMSP on all loaded SMs.
    sdtw_kernel<<<128, 256>>>(X, Y, out);
}

// round 12
// speedup vs baseline: 1.1143x; 1.0998x over previous
#include <cuda_runtime.h>

#define L2E  1.4426950408889634f
#define LN2  0.6931471805599453f
#define BIGQ (-(1 << 27))

typedef unsigned long long u64;

__device__ __forceinline__ float ex2f_(float x){ float r; asm("ex2.approx.f32 %0, %1;" : "=f"(r) : "f"(x)); return r; }
__device__ __forceinline__ float lg2f_(float x){ float r; asm("lg2.approx.f32 %0, %1;" : "=f"(r) : "f"(x)); return r; }
__device__ __forceinline__ u64 pk2(float lo, float hi){ u64 r; asm("mov.b64 %0,{%1,%2};" : "=l"(r) : "f"(lo), "f"(hi)); return r; }
__device__ __forceinline__ void upk2(float& lo, float& hi, u64 v){ asm("mov.b64 {%0,%1},%2;" : "=f"(lo), "=f"(hi) : "l"(v)); }
__device__ __forceinline__ u64 fma2(u64 a, u64 b, u64 c){ u64 r; asm("fma.rn.f32x2 %0,%1,%2,%3;" : "=l"(r) : "l"(a), "l"(b), "l"(c)); return r; }

// exact e * 2^max(dq, -126), e in [1,2), dq <= 0  (pure ALU, no MUFU)
__device__ __forceinline__ float scl_(float e, int dq){
    int d = dq < -126 ? -126 : dq;
    return __uint_as_float(__float_as_uint(e) + ((unsigned)d << 23));
}

// One warp = FOUR (a,b) pairs chained in anti-phase (+128 steps each), 4 rows/thread,
// 1 warp per SMSP (128 blocks x 128 threads). Weight-domain DP: w = e*2^q.
// The warp-boundary SHFLs are software-pipelined ONE STEP ahead: slot 3 (computed
// first each step) is shuffled immediately, ~100 instructions before its consumer
// (next step's slot 0), hiding the 26-cycle SHFL latency that a single warp
// cannot otherwise cover.
__global__ __launch_bounds__(128)
void sdtw_kernel(const float* __restrict__ X, const float* __restrict__ Y,
                 float* __restrict__ out)
{
    // 4 tiles; row j of tile t: sy[t*1152 + (j&3)*256 + c*128 + (j>>2)*4 + k]
    // nsqy = -L2E*|Y[j]|^2 at sy[t*1152 + 1024 + (j&3)*32 + (j>>2)]
    __shared__ __align__(16) float sy[4 * 1152];

    const int tid  = threadIdx.x;
    const int lane = tid & 31;
    const int wid  = tid >> 5;

    const int b0 = (blockIdx.x & 3) * 4;
    const int a  = (blockIdx.x >> 2) * 4 + wid;

    for (int rep = 0; rep < 4; ++rep) {
        int gr   = tid + rep * 128;
        int tile = gr >> 7;
        int j    = gr & 127;
        const float* yrow = Y + (size_t)(b0 + tile) * 1024 + j * 8;
        float sq = 0.f;
        int base = tile * 1152 + (j & 3) * 256 + (j >> 2) * 4;
        #pragma unroll
        for (int k = 0; k < 8; ++k) {
            float vv = yrow[k];
            sq = fmaf(vv, vv, sq);
            sy[base + (k >> 2) * 128 + (k & 3)] = vv;
        }
        sy[tile * 1152 + 1024 + (j & 3) * 32 + (j >> 2)] = sq * (-L2E);
    }

    // X: packed xs2 = +2*L2E*x ; nsqx = -L2E*|x|^2  ->  dot result = -L2E*|x-y|^2
    u64   xs2[4][4];
    float nsqx[4];
    {
        const float* xp = X + (size_t)a * 1024 + lane * 32;
        #pragma unroll
        for (int s = 0; s < 4; ++s) {
            float acc = 0.f;
            #pragma unroll
            for (int kp = 0; kp < 4; ++kp) {
                float f0 = xp[s * 8 + 2 * kp];
                float f1 = xp[s * 8 + 2 * kp + 1];
                acc = fmaf(f0, f0, fmaf(f1, f1, acc));
                xs2[s][kp] = pk2(f0 * (2.0f * L2E), f1 * (2.0f * L2E));
            }
            nsqx[s] = acc * (-L2E);
        }
    }
    __syncthreads();

    // DP state: mantissa e in [1,2), exponent q (int). Masked == q very negative.
    float e[2][4];
    int   q[2][4];
    #pragma unroll
    for (int s = 0; s < 4; ++s) {
        e[0][s] = 1.0f; e[1][s] = 1.0f;
        q[0][s] = BIGQ; q[1][s] = BIGQ;
    }

    // Y register pipeline: buffer (p)&3 holds row ja0(p) = p - 4*lane.
    u64   yp2[4][4];
    float nyq[4];
    #pragma unroll
    for (int b = 0; b < 4; ++b) {
        nyq[b] = 0.f;
        #pragma unroll
        for (int kp = 0; kp < 4; ++kp) yp2[b][kp] = 0ull;
    }

    const int lane4 = lane * 4;

    // prologue: buffer 0 <- row ja0(p=0) = -lane4 (wrapped; real only for lane 0)
    {
        unsigned jb = (unsigned)(-lane4) & 511u;
        int t   = (int)(jb >> 7) * 1152;
        int off = (int)((jb >> 2) & 31u);
        int A   = t + (int)(jb & 3u) * 256 + off * 4;
        float4 c0 = *reinterpret_cast<const float4*>(&sy[A]);
        float4 c1 = *reinterpret_cast<const float4*>(&sy[A + 128]);
        yp2[0][0] = pk2(c0.x, c0.y); yp2[0][1] = pk2(c0.z, c0.w);
        yp2[0][2] = pk2(c1.x, c1.y); yp2[0][3] = pk2(c1.z, c1.w);
        nyq[0] = sy[t + 1024 + (int)(jb & 3u) * 32 + off];
    }

    // shuffle pipeline: shC = shfl of slot3 from step p-1 (used by this step's s=0 "up"),
    //                   shP = shfl of slot3 from step p-2 (this step's s=0 "diag").
    float shCe = 1.0f, shPe = 1.0f;
    int   shCq = BIGQ, shPq = BIGQ;

    const int outA = a * 16 + b0;

    // one DP cell: softmin(aligned add) * ex2(distance), exact exponent split
    #define CELL(S, BUF, EU, QU, EL, QL, ED, QD, WI)                                   \
    {                                                                                   \
        int qm = max(max((QU), (QL)), (QD));                                            \
        float sum = (scl_((EU), (QU) - qm) + scl_((EL), (QL) - qm))                     \
                  + scl_((ED), (QD) - qm);                                              \
        u64 acc2 = pk2(nsqx[S], nyq[BUF]);                                              \
        _Pragma("unroll")                                                               \
        for (int kp = 0; kp < 4; ++kp)                                                  \
            acc2 = fma2(xs2[S][kp], yp2[BUF][kp], acc2);                                \
        float lo_, hi_; upk2(lo_, hi_, acc2);                                           \
        float w = sum * ex2f_(lo_ + hi_);                                               \
        unsigned wb = __float_as_uint(w);                                               \
        q[WI][S] = qm + (int)(wb >> 23) - 127;                                          \
        e[WI][S] = __uint_as_float((wb & 0x007FFFFFu) | 0x3F800000u);                   \
    }

    for (int p0 = 0; p0 < 640; p0 += 4) {
        const int j0      = p0 - lane4;
        const unsigned jc = (unsigned)j0 & 511u;
        const unsigned jn = (unsigned)(j0 + 4) & 511u;
        const int tOff0   = (int)(jc >> 7) * 1152;
        const int m0      = (int)((jc >> 2) & 31u);
        const int baseY0  = tOff0 + m0 * 4;
        const int qb0     = tOff0 + 1024 + m0;
        const int tOff1   = (int)(jn >> 7) * 1152;
        const int m1      = (int)((jn >> 2) & 31u);
        const int baseY1  = tOff1 + m1 * 4;
        const int qb1     = tOff1 + 1024 + m1;
        const bool bj0    = ((jc & 127u) == 0u);   // per-pair j==0 boundary: fires only at s==u
        const bool harv   = ((p0 & 127) == 124) && (p0 >= 252);

        #pragma unroll
        for (int u = 0; u < 4; ++u) {
            const int wIdx = u & 1;
            const int rIdx = wIdx ^ 1;

            // ---- slot 3 FIRST (reads prev2 q[wIdx][2] before slot 2 overwrites it) ----
            {
                float el = e[rIdx][3], ed = e[wIdx][2];
                int   ql, qd;
                if (u == 3) { ql = bj0 ? BIGQ : q[rIdx][3];  qd = bj0 ? BIGQ : q[wIdx][2]; }
                else        { ql = q[rIdx][3];               qd = q[wIdx][2]; }
                CELL(3, (u + 1) & 3, e[rIdx][2], q[rIdx][2], el, ql, ed, qd, wIdx)
            }

            // ---- shuffle slot3 for NEXT step, issued ~100 instr before its consumer ----
            const float shNe = __shfl_up_sync(0xffffffffu, e[wIdx][3], 1);
            const int   shNq = __shfl_up_sync(0xffffffffu, q[wIdx][3], 1);

            // ---- refill buffer (u+1)&3 (slot 3, its only pending reader, is done) ----
            {
                const int A = (u < 3) ? (baseY0 + (u + 1) * 256) : baseY1;
                const int b = (u + 1) & 3;
                float4 c0 = *reinterpret_cast<const float4*>(&sy[A]);
                float4 c1 = *reinterpret_cast<const float4*>(&sy[A + 128]);
                yp2[b][0] = pk2(c0.x, c0.y); yp2[b][1] = pk2(c0.z, c0.w);
                yp2[b][2] = pk2(c1.x, c1.y); yp2[b][3] = pk2(c1.z, c1.w);
                nyq[b] = (u < 3) ? sy[qb0 + (u + 1) * 32] : sy[qb1];
            }

            // ---- slots 2, 1 ----
            #pragma unroll
            for (int s = 2; s >= 1; --s) {
                float el = e[rIdx][s], ed = e[wIdx][s - 1];
                int   ql, qd;
                if (s == u) { ql = bj0 ? BIGQ : q[rIdx][s];  qd = bj0 ? BIGQ : q[wIdx][s - 1]; }
                else        { ql = q[rIdx][s];               qd = q[wIdx][s - 1]; }
                CELL(s, (u - s) & 3, e[rIdx][s - 1], q[rIdx][s - 1], el, ql, ed, qd, wIdx)
            }

            // ---- slot 0 (consumes the shuffles issued LAST step: shC/shP) ----
            {
                float eu = shCe, el, ed;
                int   qu = (lane == 0) ? BIGQ : shCq, ql, qd;
                if (u == 0) {
                    el = e[rIdx][0];  ql = bj0 ? BIGQ : q[rIdx][0];
                    if (lane == 0) { ed = 1.0f;  qd = bj0 ? 0 : BIGQ; }   // corner seed of each pair
                    else           { ed = shPe;  qd = bj0 ? BIGQ : shPq; }
                } else {
                    el = e[rIdx][0];  ql = q[rIdx][0];
                    ed = shPe;        qd = (lane == 0) ? BIGQ : shPq;
                }
                CELL(0, u & 3, eu, qu, el, ql, ed, qd, wIdx)
            }

            // harvest pair k at p = 128k + 254 (u == 2 within its block)
            if (u == 2 && harv && lane == 31) {
                int k = (p0 - 252) >> 7;
                out[outA + k] = -((float)q[0][3] + lg2f_(e[0][3])) * LN2;
            }

            // rotate shuffle pipeline
            shPe = shCe;  shPq = shCq;
            shCe = shNe;  shCq = shNq;
        }
    }
    #undef CELL
}

extern "C" void kernel_launch(void* const* d_in, const int* in_sizes, int n_in,
                              void* d_out, int out_size)
{
    const float* X = (const float*)d_in[0];
    const float* Y = (const float*)d_in[1];
    if (n_in >= 2 && in_sizes[0] < in_sizes[1]) {
        const float* t = X; X = Y; Y = t;
    }
    float* out = (float*)d_out;

    // 128 blocks x 128 threads: block = 4 a-values x one b-quad; warp = 4 chained pairs.
    // <=1 block per SM -> exactly 1 warp per SMSP, uniform load.
    sdtw_kernel<<<128, 128>>>(X, Y, out);
}